// round 6
// baseline (speedup 1.0000x reference)
#include <cuda_runtime.h>
#include <cuda_bf16.h>
#include <cstdint>
#include <math.h>

#define H 1024
#define I 2048
#define E 8
#define T 4096

// out layout: [0, T*H) routed ; [T*H] aux ; [T*H+1] z ; [T*H+2, +T*E) logits
#define OUT_AUX   (T*H)
#define OUT_Z     (T*H + 1)
#define OUT_LOG   (T*H + 2)

#define BM 128
#define BK 32
#define BN1 64      // gemm1 tile N
#define BN2 128     // gemm2 tile N
#define STR 40      // smem row stride (floats), conflict-free for 8r+2c pattern

// ---------------- device scratch (allocation-free contract) ----------------
__device__ int   g_count[E];
__device__ int   g_tok[E][T];
__device__ float g_wt[E][T];
__device__ float g_probs[T * E];
__device__ float g_z[T];
__device__ float g_inter[(size_t)E * T * I];   // permuted-I, tf32-rounded
__device__ float g_sinter[(size_t)T * I];      // shared-expert intermediate
__device__ float g_xr [(size_t)T * H];         // permuted-H, tf32-rounded
__device__ float g_gwT[(size_t)E * I * H];     // gate^T  [I][Hperm]
__device__ float g_uwT[(size_t)E * I * H];     // up^T    [I][Hperm]
__device__ float g_dwT[(size_t)E * H * I];     // down^T  [H][Iperm]
__device__ float g_sgT[(size_t)I * H];
__device__ float g_suT[(size_t)I * H];
__device__ float g_sdT[(size_t)H * I];

__device__ __forceinline__ float silu(float v) { return v / (1.0f + expf(-v)); }

__device__ __forceinline__ uint32_t tf32bits(float f) {
    uint32_t r; asm("cvt.rna.tf32.f32 %0, %1;\n" : "=r"(r) : "f"(f)); return r;
}
__device__ __forceinline__ uint32_t smem_u32(const void* p) {
    return (uint32_t)__cvta_generic_to_shared(p);
}
__device__ __forceinline__ void cp16(uint32_t dst, const void* src, bool pred) {
    int sz = pred ? 16 : 0;
    asm volatile("cp.async.cg.shared.global [%0], [%1], 16, %2;\n"
                 :: "r"(dst), "l"(src), "r"(sz));
}
__device__ __forceinline__ void cp_commit() { asm volatile("cp.async.commit_group;\n"); }
__device__ __forceinline__ void cp_wait1()  { asm volatile("cp.async.wait_group 1;\n"); }

__device__ __forceinline__ void mma_tf32(float* c, const uint32_t* a, const uint32_t* b) {
    asm volatile("mma.sync.aligned.m16n8k8.row.col.f32.tf32.tf32.f32 "
                 "{%0,%1,%2,%3}, {%4,%5,%6,%7}, {%8,%9}, {%0,%1,%2,%3};\n"
                 : "+f"(c[0]), "+f"(c[1]), "+f"(c[2]), "+f"(c[3])
                 : "r"(a[0]), "r"(a[1]), "r"(a[2]), "r"(a[3]),
                   "r"(b[0]), "r"(b[1]));
}

// permuted k order within each 8-group: pos -> logical
// [k0,k4,k1,k5,k2,k6,k3,k7]
__device__ __host__ __forceinline__ int perm_logical(int pos) {
    return (pos & 1) ? ((pos >> 1) + 4) : (pos >> 1);
}
// logical -> pos
__device__ __forceinline__ int perm_pos(int l) {
    return (l < 4) ? (2 * l) : (2 * (l - 4) + 1);
}

// ---------------- prep kernels ----------------
// x: round + permute k within 8-groups (rows stay)
__global__ void permute_round_x(const float* __restrict__ src, float* __restrict__ dst, int n) {
    int i = blockIdx.x * blockDim.x + threadIdx.x;
    if (i >= n) return;
    int pos = i & 7;
    float v = src[(i & ~7) + perm_logical(pos)];
    dst[i] = __uint_as_float(tf32bits(v));
}

// src [K][N] row-major -> dst [N][Kperm], tf32-rounded; z selects matrix
__global__ void transpose_round_perm(const float* __restrict__ src, float* __restrict__ dst,
                                     int K, int N) {
    __shared__ float tile[32][33];
    size_t moff = (size_t)blockIdx.z * (size_t)K * N;
    int k0 = blockIdx.y * 32, n0 = blockIdx.x * 32;
    int tx = threadIdx.x & 31, ty = threadIdx.x >> 5;   // 256 = 32x8
#pragma unroll
    for (int r = ty; r < 32; r += 8)
        tile[r][tx] = src[moff + (size_t)(k0 + r) * N + n0 + tx];
    __syncthreads();
    int grp = tx >> 3, pos = tx & 7;
    int kl = grp * 8 + perm_logical(pos);
#pragma unroll
    for (int r = ty; r < 32; r += 8)
        dst[moff + (size_t)(n0 + r) * K + k0 + tx] =
            __uint_as_float(tf32bits(tile[kl][r]));
}

__global__ void zero_routed(float* __restrict__ out) {
    int i = blockIdx.x * blockDim.x + threadIdx.x;
    reinterpret_cast<float4*>(out)[i] = make_float4(0.f, 0.f, 0.f, 0.f);
}

__global__ void init_kernel() {
    int i = threadIdx.x;
    if (i < E) g_count[i] = 0;
}

// ---------------- router ----------------
__global__ void router_kernel(const float* __restrict__ x,
                              const float* __restrict__ rw,
                              float* __restrict__ out_logits) {
    int t = blockIdx.x;
    int tid = threadIdx.x;
    const float* xr = x + (size_t)t * H;

    float p[E];
#pragma unroll
    for (int e = 0; e < E; e++) p[e] = 0.0f;
    for (int h = tid; h < H; h += 256) {
        float xv = xr[h];
        const float* r = rw + (size_t)h * E;
#pragma unroll
        for (int e = 0; e < E; e++) p[e] += xv * r[e];
    }
#pragma unroll
    for (int off = 16; off > 0; off >>= 1)
#pragma unroll
        for (int e = 0; e < E; e++)
            p[e] += __shfl_down_sync(0xFFFFFFFFu, p[e], off);

    __shared__ float sred[8][E];
    int warp = tid >> 5, lane = tid & 31;
    if (lane == 0)
#pragma unroll
        for (int e = 0; e < E; e++) sred[warp][e] = p[e];
    __syncthreads();

    if (tid == 0) {
        float logit[E];
#pragma unroll
        for (int e = 0; e < E; e++) {
            float s = 0.0f;
#pragma unroll
            for (int w = 0; w < 8; w++) s += sred[w][e];
            logit[e] = s;
            out_logits[(size_t)t * E + e] = s;
        }
        float mx = logit[0];
#pragma unroll
        for (int e = 1; e < E; e++) mx = fmaxf(mx, logit[e]);
        float se = 0.0f, pr[E];
#pragma unroll
        for (int e = 0; e < E; e++) { pr[e] = expf(logit[e] - mx); se += pr[e]; }
        float inv = 1.0f / se;
#pragma unroll
        for (int e = 0; e < E; e++) { pr[e] *= inv; g_probs[(size_t)t * E + e] = pr[e]; }
        float lse = mx + logf(se);
        g_z[t] = lse * lse;

        int i0 = 0;
#pragma unroll
        for (int e = 1; e < E; e++) if (pr[e] > pr[i0]) i0 = e;
        int i1 = (i0 == 0) ? 1 : 0;
#pragma unroll
        for (int e = 0; e < E; e++) if (e != i0 && pr[e] > pr[i1]) i1 = e;

        float w0 = pr[i0], w1 = pr[i1];
        float ws = 1.0f / (w0 + w1);
        w0 *= ws; w1 *= ws;
        int s0 = atomicAdd(&g_count[i0], 1);
        g_tok[i0][s0] = t; g_wt[i0][s0] = w0;
        int s1 = atomicAdd(&g_count[i1], 1);
        g_tok[i1][s1] = t; g_wt[i1][s1] = w1;
    }
}

// ---------------- GEMM1: inter = tf32(silu(X@G) * (X@U)) ----------------
// grid (I/BN1, T/BM, E+1); z==E -> shared expert. Warp tile 32x32 (4x2 warps).
__global__ void __launch_bounds__(256, 2)
gemm1_kernel() {
    extern __shared__ float sm[];
    float* As = sm;                       // 2 * BM * STR
    float* Bg = As + 2 * BM * STR;        // 2 * BN1 * STR
    float* Bu = Bg + 2 * BN1 * STR;

    int z = blockIdx.z;
    bool shm = (z == E);
    int e   = shm ? 0 : z;
    int cnt = shm ? T : g_count[e];
    int m0  = blockIdx.y * BM;
    if (m0 >= cnt) return;
    int n0 = blockIdx.x * BN1;

    const float* gsrc = shm ? g_sgT : (g_gwT + (size_t)e * I * H);   // [I][Hperm]
    const float* usrc = shm ? g_suT : (g_uwT + (size_t)e * I * H);
    float* ibase = shm ? g_sinter : (g_inter + (size_t)e * T * I);

    int tid = threadIdx.x;
    int lane = tid & 31, warp = tid >> 5;
    int wm = warp & 3, wn = warp >> 2;
    int r = lane >> 2, c = lane & 3;

    // A: 4 chunks/thread
    const float* asrc[4]; bool aval[4]; uint32_t aoff[4];
#pragma unroll
    for (int j = 0; j < 4; j++) {
        int item = tid + j * 256;
        int arow = item >> 3, achk = item & 7;
        int rr = m0 + arow;
        bool v = rr < cnt;
        int token = shm ? rr : (v ? g_tok[e][rr] : 0);
        asrc[j] = g_xr + (size_t)token * H + achk * 4;
        aval[j] = v;
        aoff[j] = (uint32_t)(arow * STR + achk * 4);
    }
    // B: 2 chunks/thread per matrix (64 rows x 8 chunks = 512)
    const float* gptr[2]; const float* uptr[2]; uint32_t boff[2];
#pragma unroll
    for (int j = 0; j < 2; j++) {
        int item = tid + j * 256;
        int brow = item >> 3, bchk = item & 7;
        gptr[j] = gsrc + (size_t)(n0 + brow) * H + bchk * 4;
        uptr[j] = usrc + (size_t)(n0 + brow) * H + bchk * 4;
        boff[j] = (uint32_t)(brow * STR + bchk * 4);
    }

    float accG[2][4][4] = {}, accU[2][4][4] = {};

#pragma unroll
    for (int j = 0; j < 4; j++) cp16(smem_u32(As + aoff[j]), asrc[j], aval[j]);
#pragma unroll
    for (int j = 0; j < 2; j++) {
        cp16(smem_u32(Bg + boff[j]), gptr[j], true);
        cp16(smem_u32(Bu + boff[j]), uptr[j], true);
    }
    cp_commit();

    const int NIT = H / BK;   // 32
    for (int it = 0; it < NIT; ++it) {
        if (it + 1 < NIT) {
            int k0 = (it + 1) * BK;
            int sa = ((it + 1) & 1) ? BM * STR : 0;
            int sb = ((it + 1) & 1) ? BN1 * STR : 0;
#pragma unroll
            for (int j = 0; j < 4; j++)
                cp16(smem_u32(As + sa + aoff[j]), asrc[j] + k0, aval[j]);
#pragma unroll
            for (int j = 0; j < 2; j++) {
                cp16(smem_u32(Bg + sb + boff[j]), gptr[j] + k0, true);
                cp16(smem_u32(Bu + sb + boff[j]), uptr[j] + k0, true);
            }
        }
        cp_commit();
        cp_wait1();
        __syncthreads();
        const float* Asl = As + ((it & 1) ? BM * STR : 0);
        const float* Bgl = Bg + ((it & 1) ? BN1 * STR : 0);
        const float* Bul = Bu + ((it & 1) ? BN1 * STR : 0);
#pragma unroll
        for (int ks = 0; ks < 4; ks++) {
            uint32_t a[2][4];
#pragma unroll
            for (int mt = 0; mt < 2; mt++) {
                int mr = wm * 32 + mt * 16;
                float2 lo = *reinterpret_cast<const float2*>(&Asl[(mr + r    ) * STR + ks * 8 + 2 * c]);
                float2 hi = *reinterpret_cast<const float2*>(&Asl[(mr + r + 8) * STR + ks * 8 + 2 * c]);
                a[mt][0] = __float_as_uint(lo.x);
                a[mt][1] = __float_as_uint(hi.x);
                a[mt][2] = __float_as_uint(lo.y);
                a[mt][3] = __float_as_uint(hi.y);
            }
#pragma unroll
            for (int nt = 0; nt < 4; nt++) {
                int nc = wn * 32 + nt * 8 + r;
                float2 gv = *reinterpret_cast<const float2*>(&Bgl[nc * STR + ks * 8 + 2 * c]);
                float2 uv = *reinterpret_cast<const float2*>(&Bul[nc * STR + ks * 8 + 2 * c]);
                uint32_t bg[2] = { __float_as_uint(gv.x), __float_as_uint(gv.y) };
                uint32_t bu[2] = { __float_as_uint(uv.x), __float_as_uint(uv.y) };
#pragma unroll
                for (int mt = 0; mt < 2; mt++) {
                    mma_tf32(accG[mt][nt], a[mt], bg);
                    mma_tf32(accU[mt][nt], a[mt], bu);
                }
            }
        }
        __syncthreads();
    }

    // epilogue: silu(g)*u, tf32-rounded, written at PERMUTED I positions
#pragma unroll
    for (int mt = 0; mt < 2; mt++) {
#pragma unroll
        for (int hrow = 0; hrow < 2; hrow++) {
            int rr = m0 + wm * 32 + mt * 16 + r + hrow * 8;
            if (rr >= cnt) continue;
            float* orow = ibase + (size_t)rr * I;
#pragma unroll
            for (int nt = 0; nt < 4; nt++) {
                int gbase = n0 + wn * 32 + nt * 8;
                float g0 = accG[mt][nt][hrow * 2 + 0];
                float g1 = accG[mt][nt][hrow * 2 + 1];
                float u0 = accU[mt][nt][hrow * 2 + 0];
                float u1 = accU[mt][nt][hrow * 2 + 1];
                orow[gbase + perm_pos(2 * c    )] = __uint_as_float(tf32bits(silu(g0) * u0));
                orow[gbase + perm_pos(2 * c + 1)] = __uint_as_float(tf32bits(silu(g1) * u1));
            }
        }
    }
}

// ---------------- GEMM2: routed += w * (inter @ D) ----------------
// grid (H/BN2, T/BM, E+1); z==E -> shared (w=1). Warp tile 32x64 (4x2 warps).
__global__ void __launch_bounds__(256, 2)
gemm2_kernel(float* __restrict__ routed) {
    extern __shared__ float sm[];
    float* As = sm;                       // 2 * BM * STR
    float* Bd = As + 2 * BM * STR;        // 2 * BN2 * STR

    int z = blockIdx.z;
    bool shm = (z == E);
    int e   = shm ? 0 : z;
    int cnt = shm ? T : g_count[e];
    int m0  = blockIdx.y * BM;
    if (m0 >= cnt) return;
    int n0 = blockIdx.x * BN2;

    const float* dsrc = shm ? g_sdT : (g_dwT + (size_t)e * H * I);   // [H][Iperm]
    const float* inter = shm ? g_sinter : (g_inter + (size_t)e * T * I);

    int tid = threadIdx.x;
    int lane = tid & 31, warp = tid >> 5;
    int wm = warp & 3, wn = warp >> 2;
    int r = lane >> 2, c = lane & 3;

    const float* asrc[4]; bool aval[4]; uint32_t aoff[4];
#pragma unroll
    for (int j = 0; j < 4; j++) {
        int item = tid + j * 256;
        int arow = item >> 3, achk = item & 7;
        int rr = m0 + arow;
        bool v = rr < cnt;
        asrc[j] = inter + (size_t)(v ? rr : 0) * I + achk * 4;
        aval[j] = v;
        aoff[j] = (uint32_t)(arow * STR + achk * 4);
    }
    // B: 128 rows x 8 chunks = 1024 -> 4/thread
    const float* dptr[4]; uint32_t boff[4];
#pragma unroll
    for (int j = 0; j < 4; j++) {
        int item = tid + j * 256;
        int brow = item >> 3, bchk = item & 7;
        dptr[j] = dsrc + (size_t)(n0 + brow) * I + bchk * 4;
        boff[j] = (uint32_t)(brow * STR + bchk * 4);
    }

    float acc[2][8][4] = {};

#pragma unroll
    for (int j = 0; j < 4; j++) cp16(smem_u32(As + aoff[j]), asrc[j], aval[j]);
#pragma unroll
    for (int j = 0; j < 4; j++) cp16(smem_u32(Bd + boff[j]), dptr[j], true);
    cp_commit();

    const int NIT = I / BK;   // 64
    for (int it = 0; it < NIT; ++it) {
        if (it + 1 < NIT) {
            int k0 = (it + 1) * BK;
            int sa = ((it + 1) & 1) ? BM * STR : 0;
            int sb = ((it + 1) & 1) ? BN2 * STR : 0;
#pragma unroll
            for (int j = 0; j < 4; j++)
                cp16(smem_u32(As + sa + aoff[j]), asrc[j] + k0, aval[j]);
#pragma unroll
            for (int j = 0; j < 4; j++)
                cp16(smem_u32(Bd + sb + boff[j]), dptr[j] + k0, true);
        }
        cp_commit();
        cp_wait1();
        __syncthreads();
        const float* Asl = As + ((it & 1) ? BM * STR : 0);
        const float* Bdl = Bd + ((it & 1) ? BN2 * STR : 0);
#pragma unroll
        for (int ks = 0; ks < 4; ks++) {
            uint32_t a[2][4];
#pragma unroll
            for (int mt = 0; mt < 2; mt++) {
                int mr = wm * 32 + mt * 16;
                float2 lo = *reinterpret_cast<const float2*>(&Asl[(mr + r    ) * STR + ks * 8 + 2 * c]);
                float2 hi = *reinterpret_cast<const float2*>(&Asl[(mr + r + 8) * STR + ks * 8 + 2 * c]);
                a[mt][0] = __float_as_uint(lo.x);
                a[mt][1] = __float_as_uint(hi.x);
                a[mt][2] = __float_as_uint(lo.y);
                a[mt][3] = __float_as_uint(hi.y);
            }
#pragma unroll
            for (int nt = 0; nt < 8; nt++) {
                int nc = wn * 64 + nt * 8 + r;
                float2 dv = *reinterpret_cast<const float2*>(&Bdl[nc * STR + ks * 8 + 2 * c]);
                uint32_t bb[2] = { __float_as_uint(dv.x), __float_as_uint(dv.y) };
#pragma unroll
                for (int mt = 0; mt < 2; mt++)
                    mma_tf32(acc[mt][nt], a[mt], bb);
            }
        }
        __syncthreads();
    }

#pragma unroll
    for (int mt = 0; mt < 2; mt++) {
#pragma unroll
        for (int hrow = 0; hrow < 2; hrow++) {
            int rr = m0 + wm * 32 + mt * 16 + r + hrow * 8;
            if (rr >= cnt) continue;
            int token = shm ? rr : g_tok[e][rr];
            float w = shm ? 1.0f : g_wt[e][rr];
            float* dst = routed + (size_t)token * H;
#pragma unroll
            for (int nt = 0; nt < 8; nt++) {
                int col = n0 + wn * 64 + nt * 8 + 2 * c;
                atomicAdd(dst + col + 0, w * acc[mt][nt][hrow * 2 + 0]);
                atomicAdd(dst + col + 1, w * acc[mt][nt][hrow * 2 + 1]);
            }
        }
    }
}

// ---------------- finalize losses ----------------
__global__ void finalize_kernel(float* __restrict__ out) {
    int tid = threadIdx.x;
    float ps[E];
#pragma unroll
    for (int e = 0; e < E; e++) ps[e] = 0.0f;
    float zs = 0.0f;
    for (int t = tid; t < T; t += 256) {
        zs += g_z[t];
#pragma unroll
        for (int e = 0; e < E; e++) ps[e] += g_probs[(size_t)t * E + e];
    }
#pragma unroll
    for (int off = 16; off > 0; off >>= 1) {
        zs += __shfl_down_sync(0xFFFFFFFFu, zs, off);
#pragma unroll
        for (int e = 0; e < E; e++)
            ps[e] += __shfl_down_sync(0xFFFFFFFFu, ps[e], off);
    }
    __shared__ float sp[8][E];
    __shared__ float sz[8];
    int warp = tid >> 5, lane = tid & 31;
    if (lane == 0) {
        sz[warp] = zs;
#pragma unroll
        for (int e = 0; e < E; e++) sp[warp][e] = ps[e];
    }
    __syncthreads();
    if (tid == 0) {
        float ztot = 0.0f, ptot[E];
#pragma unroll
        for (int e = 0; e < E; e++) ptot[e] = 0.0f;
#pragma unroll
        for (int w = 0; w < 8; w++) {
            ztot += sz[w];
#pragma unroll
            for (int e = 0; e < E; e++) ptot[e] += sp[w][e];
        }
        float aux = 0.0f;
#pragma unroll
        for (int e = 0; e < E; e++) {
            float tpe = 0.5f * (float)g_count[e] / (float)T;
            float ppe = ptot[e] / (float)T;
            aux += tpe * ppe;
        }
        out[OUT_AUX] = (float)E * aux;
        out[OUT_Z]   = ztot / (float)T;
    }
}

// ---------------- launch ----------------
extern "C" void kernel_launch(void* const* d_in, const int* in_sizes, int n_in,
                              void* d_out, int out_size) {
    const float* x  = (const float*)d_in[0];
    const float* rw = (const float*)d_in[1];
    const float* gw = (const float*)d_in[2];
    const float* uw = (const float*)d_in[3];
    const float* dw = (const float*)d_in[4];
    const float* sg = (const float*)d_in[5];
    const float* su = (const float*)d_in[6];
    const float* sd = (const float*)d_in[7];
    float* out = (float*)d_out;

    const int SMEM1 = (2 * BM * STR + 4 * BN1 * STR) * 4;   // 81920
    const int SMEM2 = (2 * BM * STR + 2 * BN2 * STR) * 4;   // 81920
    cudaFuncSetAttribute(gemm1_kernel, cudaFuncAttributeMaxDynamicSharedMemorySize, SMEM1);
    cudaFuncSetAttribute(gemm2_kernel, cudaFuncAttributeMaxDynamicSharedMemorySize, SMEM2);

    float* xr;  cudaGetSymbolAddress((void**)&xr,  g_xr);
    float* gwT; cudaGetSymbolAddress((void**)&gwT, g_gwT);
    float* uwT; cudaGetSymbolAddress((void**)&uwT, g_uwT);
    float* dwT; cudaGetSymbolAddress((void**)&dwT, g_dwT);
    float* sgT; cudaGetSymbolAddress((void**)&sgT, g_sgT);
    float* suT; cudaGetSymbolAddress((void**)&suT, g_suT);
    float* sdT; cudaGetSymbolAddress((void**)&sdT, g_sdT);

    // prep: tf32 round + transpose + k-permutation
    permute_round_x<<<(T * H + 255) / 256, 256>>>(x, xr, T * H);
    transpose_round_perm<<<dim3(I / 32, H / 32, E), 256>>>(gw, gwT, H, I);
    transpose_round_perm<<<dim3(I / 32, H / 32, E), 256>>>(uw, uwT, H, I);
    transpose_round_perm<<<dim3(H / 32, I / 32, E), 256>>>(dw, dwT, I, H);
    transpose_round_perm<<<dim3(I / 32, H / 32, 1), 256>>>(sg, sgT, H, I);
    transpose_round_perm<<<dim3(I / 32, H / 32, 1), 256>>>(su, suT, H, I);
    transpose_round_perm<<<dim3(H / 32, I / 32, 1), 256>>>(sd, sdT, I, H);

    init_kernel<<<1, 32>>>();
    zero_routed<<<T * H / 4 / 256, 256>>>(out);
    router_kernel<<<T, 256>>>(x, rw, out + OUT_LOG);

    gemm1_kernel<<<dim3(I / BN1, T / BM, E + 1), 256, SMEM1>>>();
    gemm2_kernel<<<dim3(H / BN2, T / BM, E + 1), 256, SMEM2>>>(out);

    finalize_kernel<<<1, 256>>>(out);
}

// round 8
// speedup vs baseline: 1.0360x; 1.0360x over previous
#include <cuda_runtime.h>
#include <cuda_bf16.h>
#include <cstdint>
#include <math.h>

#define H 1024
#define I 2048
#define E 8
#define T 4096

// out layout: [0, T*H) routed ; [T*H] aux ; [T*H+1] z ; [T*H+2, +T*E) logits
#define OUT_AUX   (T*H)
#define OUT_Z     (T*H + 1)
#define OUT_LOG   (T*H + 2)

#define BM 128
#define BN 128
#define BK 32
#define ASTR 36     // A smem row stride (floats)
#define BSTR 136    // B smem row stride (floats)
#define SMEMG ((2 * BM * ASTR + 2 * BK * BSTR) * 4)   // 71680 bytes

// ---------------- device scratch (allocation-free contract) ----------------
__device__ int   g_count[E];
__device__ int   g_tok[E][T];
__device__ float g_wt[E][T];
__device__ float g_probs[T * E];
__device__ float g_z[T];
// gemm1 output [gate | up]; after swiglu pass, first I cols hold tf32(silu(g)*u)
__device__ float g_gu[(size_t)E * T * 2 * I];
__device__ float g_sgu[(size_t)T * 2 * I];
__device__ float g_xr [(size_t)T * H];           // tf32-rounded x
__device__ float g_gwr[(size_t)E * H * I];       // tf32-rounded weights (orig layout)
__device__ float g_uwr[(size_t)E * H * I];
__device__ float g_dwr[(size_t)E * I * H];
__device__ float g_sgr[(size_t)H * I];
__device__ float g_sur[(size_t)H * I];
__device__ float g_sdr[(size_t)I * H];

__device__ __forceinline__ float silu(float v) { return v / (1.0f + expf(-v)); }

__device__ __forceinline__ uint32_t tf32bits(float f) {
    uint32_t r; asm("cvt.rna.tf32.f32 %0, %1;\n" : "=r"(r) : "f"(f)); return r;
}
__device__ __forceinline__ uint32_t smem_u32(const void* p) {
    return (uint32_t)__cvta_generic_to_shared(p);
}
__device__ __forceinline__ void cp16(uint32_t dst, const void* src, bool pred) {
    int sz = pred ? 16 : 0;
    asm volatile("cp.async.cg.shared.global [%0], [%1], 16, %2;\n"
                 :: "r"(dst), "l"(src), "r"(sz));
}
__device__ __forceinline__ void cp_commit() { asm volatile("cp.async.commit_group;\n"); }
__device__ __forceinline__ void cp_wait1()  { asm volatile("cp.async.wait_group 1;\n"); }

__device__ __forceinline__ void mma_tf32(float* c, const uint32_t* a, const uint32_t* b) {
    asm volatile("mma.sync.aligned.m16n8k8.row.col.f32.tf32.tf32.f32 "
                 "{%0,%1,%2,%3}, {%4,%5,%6,%7}, {%8,%9}, {%0,%1,%2,%3};\n"
                 : "+f"(c[0]), "+f"(c[1]), "+f"(c[2]), "+f"(c[3])
                 : "r"(a[0]), "r"(a[1]), "r"(a[2]), "r"(a[3]),
                   "r"(b[0]), "r"(b[1]));
}

// ---------------- prep ----------------
__global__ void round_kernel(const float* __restrict__ src, float* __restrict__ dst, int n4) {
    int i = blockIdx.x * blockDim.x + threadIdx.x;
    if (i >= n4) return;
    float4 v = reinterpret_cast<const float4*>(src)[i];
    v.x = __uint_as_float(tf32bits(v.x));
    v.y = __uint_as_float(tf32bits(v.y));
    v.z = __uint_as_float(tf32bits(v.z));
    v.w = __uint_as_float(tf32bits(v.w));
    reinterpret_cast<float4*>(dst)[i] = v;
}

__global__ void zero_routed(float* __restrict__ out) {
    int i = blockIdx.x * blockDim.x + threadIdx.x;
    reinterpret_cast<float4*>(out)[i] = make_float4(0.f, 0.f, 0.f, 0.f);
}

__global__ void init_kernel() {
    int i = threadIdx.x;
    if (i < E) g_count[i] = 0;
}

// ---------------- router ----------------
__global__ void router_kernel(const float* __restrict__ x,
                              const float* __restrict__ rw,
                              float* __restrict__ out_logits) {
    int t = blockIdx.x;
    int tid = threadIdx.x;
    const float* xr = x + (size_t)t * H;

    float p[E];
#pragma unroll
    for (int e = 0; e < E; e++) p[e] = 0.0f;
    for (int h = tid; h < H; h += 256) {
        float xv = xr[h];
        const float* r = rw + (size_t)h * E;
#pragma unroll
        for (int e = 0; e < E; e++) p[e] += xv * r[e];
    }
#pragma unroll
    for (int off = 16; off > 0; off >>= 1)
#pragma unroll
        for (int e = 0; e < E; e++)
            p[e] += __shfl_down_sync(0xFFFFFFFFu, p[e], off);

    __shared__ float sred[8][E];
    int warp = tid >> 5, lane = tid & 31;
    if (lane == 0)
#pragma unroll
        for (int e = 0; e < E; e++) sred[warp][e] = p[e];
    __syncthreads();

    if (tid == 0) {
        float logit[E];
#pragma unroll
        for (int e = 0; e < E; e++) {
            float s = 0.0f;
#pragma unroll
            for (int w = 0; w < 8; w++) s += sred[w][e];
            logit[e] = s;
            out_logits[(size_t)t * E + e] = s;
        }
        float mx = logit[0];
#pragma unroll
        for (int e = 1; e < E; e++) mx = fmaxf(mx, logit[e]);
        float se = 0.0f, pr[E];
#pragma unroll
        for (int e = 0; e < E; e++) { pr[e] = expf(logit[e] - mx); se += pr[e]; }
        float inv = 1.0f / se;
#pragma unroll
        for (int e = 0; e < E; e++) { pr[e] *= inv; g_probs[(size_t)t * E + e] = pr[e]; }
        float lse = mx + logf(se);
        g_z[t] = lse * lse;

        int i0 = 0;
#pragma unroll
        for (int e = 1; e < E; e++) if (pr[e] > pr[i0]) i0 = e;
        int i1 = (i0 == 0) ? 1 : 0;
#pragma unroll
        for (int e = 0; e < E; e++) if (e != i0 && pr[e] > pr[i1]) i1 = e;

        float w0 = pr[i0], w1 = pr[i1];
        float ws = 1.0f / (w0 + w1);
        w0 *= ws; w1 *= ws;
        int s0 = atomicAdd(&g_count[i0], 1);
        g_tok[i0][s0] = t; g_wt[i0][s0] = w0;
        int s1 = atomicAdd(&g_count[i1], 1);
        g_tok[i1][s1] = t; g_wt[i1][s1] = w1;
    }
}

// ---------------- GEMM1 (plain): gu = X @ [G | U] ----------------
// grid (2I/BN, T/BM, E+1); z==E -> shared expert.
// 8 warps 2x4; warp tile 64x32 (mt=4, nt=4).
__global__ void __launch_bounds__(256)
gemm1_kernel() {
    extern __shared__ float sm[];
    float* As = sm;                       // 2 * BM * ASTR
    float* Bs = As + 2 * BM * ASTR;       // 2 * BK * BSTR

    int z = blockIdx.z;
    bool shm = (z == E);
    int e   = shm ? 0 : z;
    int cnt = shm ? T : g_count[e];
    int m0  = blockIdx.y * BM;
    if (m0 >= cnt) return;
    int n0 = blockIdx.x * BN;             // 0 .. 2I-1

    const float* wsrc;
    int wcol;
    if (n0 < I) { wsrc = shm ? g_sgr : (g_gwr + (size_t)e * H * I); wcol = n0; }
    else        { wsrc = shm ? g_sur : (g_uwr + (size_t)e * H * I); wcol = n0 - I; }
    float* gu = shm ? g_sgu : (g_gu + (size_t)e * T * 2 * I);

    int tid = threadIdx.x;
    int lane = tid & 31, warp = tid >> 5;
    int wm = warp >> 2, wn = warp & 3;          // 2 x 4
    int r = lane >> 2, c = lane & 3;

    // A: 4 chunks/thread (128 rows x 8 chunks)
    const float* asrc[4]; bool aval[4]; uint32_t aoff[4];
#pragma unroll
    for (int j = 0; j < 4; j++) {
        int item = tid + j * 256;
        int arow = item >> 3, achk = item & 7;
        int rr = m0 + arow;
        bool v = rr < cnt;
        int token = shm ? rr : (v ? g_tok[e][rr] : 0);
        asrc[j] = g_xr + (size_t)token * H + achk * 4;
        aval[j] = v;
        aoff[j] = (uint32_t)(arow * ASTR + achk * 4);
    }
    // B: 4 chunks/thread (32 k-rows x 32 chunks)
    const float* bptr[4]; uint32_t boff[4];
#pragma unroll
    for (int j = 0; j < 4; j++) {
        int item = tid + j * 256;
        int brow = item >> 5, bchk = item & 31;
        bptr[j] = wsrc + (size_t)brow * I + wcol + bchk * 4;
        boff[j] = (uint32_t)(brow * BSTR + bchk * 4);
    }

    float acc[4][4][4] = {};

#pragma unroll
    for (int j = 0; j < 4; j++) cp16(smem_u32(As + aoff[j]), asrc[j], aval[j]);
#pragma unroll
    for (int j = 0; j < 4; j++) cp16(smem_u32(Bs + boff[j]), bptr[j], true);
    cp_commit();

    const int NIT = H / BK;   // 32
    for (int it = 0; it < NIT; ++it) {
        if (it + 1 < NIT) {
            int k0 = (it + 1) * BK;
            int sa = ((it + 1) & 1) ? BM * ASTR : 0;
            int sb = ((it + 1) & 1) ? BK * BSTR : 0;
#pragma unroll
            for (int j = 0; j < 4; j++)
                cp16(smem_u32(As + sa + aoff[j]), asrc[j] + k0, aval[j]);
#pragma unroll
            for (int j = 0; j < 4; j++)
                cp16(smem_u32(Bs + sb + boff[j]), bptr[j] + (size_t)k0 * I, true);
        }
        cp_commit();
        cp_wait1();
        __syncthreads();
        const float* Asl = As + ((it & 1) ? BM * ASTR : 0);
        const float* Bsl = Bs + ((it & 1) ? BK * BSTR : 0);
#pragma unroll
        for (int ks = 0; ks < 4; ks++) {
            uint32_t a[4][4];
#pragma unroll
            for (int mt = 0; mt < 4; mt++) {
                int mr = wm * 64 + mt * 16;
                a[mt][0] = __float_as_uint(Asl[(mr + r    ) * ASTR + ks * 8 + c    ]);
                a[mt][1] = __float_as_uint(Asl[(mr + r + 8) * ASTR + ks * 8 + c    ]);
                a[mt][2] = __float_as_uint(Asl[(mr + r    ) * ASTR + ks * 8 + c + 4]);
                a[mt][3] = __float_as_uint(Asl[(mr + r + 8) * ASTR + ks * 8 + c + 4]);
            }
#pragma unroll
            for (int nt = 0; nt < 4; nt++) {
                int nc = wn * 32 + nt * 8 + r;
                uint32_t b[2];
                b[0] = __float_as_uint(Bsl[(ks * 8 + c    ) * BSTR + nc]);
                b[1] = __float_as_uint(Bsl[(ks * 8 + c + 4) * BSTR + nc]);
#pragma unroll
                for (int mt = 0; mt < 4; mt++)
                    mma_tf32(acc[mt][nt], a[mt], b);
            }
        }
        __syncthreads();
    }

    // plain store into gu (row stride 2I)
#pragma unroll
    for (int mt = 0; mt < 4; mt++) {
#pragma unroll
        for (int hrow = 0; hrow < 2; hrow++) {
            int rr = m0 + wm * 64 + mt * 16 + r + hrow * 8;
            if (rr >= cnt) continue;
            float* orow = gu + (size_t)rr * 2 * I;
#pragma unroll
            for (int nt = 0; nt < 4; nt++) {
                int col = n0 + wn * 32 + nt * 8 + 2 * c;
                float2 o = make_float2(acc[mt][nt][hrow * 2 + 0],
                                       acc[mt][nt][hrow * 2 + 1]);
                *reinterpret_cast<float2*>(orow + col) = o;
            }
        }
    }
}

// ---------------- SwiGLU in-place: gu[:, 0:I) = tf32(silu(g) * u) ---------
// grid (I/1024, T, E+1), 256 threads, 4 floats each; valid rows only
__global__ void swiglu_kernel() {
    int z = blockIdx.z;
    bool shm = (z == E);
    int e   = shm ? 0 : z;
    int cnt = shm ? T : g_count[e];
    int rr  = blockIdx.y;
    if (rr >= cnt) return;
    float* gu = (shm ? g_sgu : (g_gu + (size_t)e * T * 2 * I)) + (size_t)rr * 2 * I;
    int i = (blockIdx.x * 256 + threadIdx.x) * 4;
    float4 g = *reinterpret_cast<const float4*>(gu + i);
    float4 u = *reinterpret_cast<const float4*>(gu + I + i);
    float4 o;
    o.x = __uint_as_float(tf32bits(silu(g.x) * u.x));
    o.y = __uint_as_float(tf32bits(silu(g.y) * u.y));
    o.z = __uint_as_float(tf32bits(silu(g.z) * u.z));
    o.w = __uint_as_float(tf32bits(silu(g.w) * u.w));
    *reinterpret_cast<float4*>(gu + i) = o;
}

// ---------------- GEMM2: routed += w * (inter @ D) ----------------
// inter = first I cols of gu rows (stride 2I).
// grid (H/BN, T/BM, E+1); z==E -> shared (w=1). Warp tile 64x32.
__global__ void __launch_bounds__(256)
gemm2_kernel(float* __restrict__ routed) {
    extern __shared__ float sm[];
    float* As = sm;
    float* Bs = As + 2 * BM * ASTR;

    int z = blockIdx.z;
    bool shm = (z == E);
    int e   = shm ? 0 : z;
    int cnt = shm ? T : g_count[e];
    int m0  = blockIdx.y * BM;
    if (m0 >= cnt) return;
    int n0 = blockIdx.x * BN;

    const float* dsrc = shm ? g_sdr : (g_dwr + (size_t)e * I * H);
    const float* inter = shm ? g_sgu : (g_gu + (size_t)e * T * 2 * I);

    int tid = threadIdx.x;
    int lane = tid & 31, warp = tid >> 5;
    int wm = warp >> 2, wn = warp & 3;
    int r = lane >> 2, c = lane & 3;

    const float* asrc[4]; bool aval[4]; uint32_t aoff[4];
#pragma unroll
    for (int j = 0; j < 4; j++) {
        int item = tid + j * 256;
        int arow = item >> 3, achk = item & 7;
        int rr = m0 + arow;
        bool v = rr < cnt;
        asrc[j] = inter + (size_t)(v ? rr : 0) * 2 * I + achk * 4;
        aval[j] = v;
        aoff[j] = (uint32_t)(arow * ASTR + achk * 4);
    }
    const float* bptr[4]; uint32_t boff[4];
#pragma unroll
    for (int j = 0; j < 4; j++) {
        int item = tid + j * 256;
        int brow = item >> 5, bchk = item & 31;
        bptr[j] = dsrc + (size_t)brow * H + n0 + bchk * 4;
        boff[j] = (uint32_t)(brow * BSTR + bchk * 4);
    }

    float acc[4][4][4] = {};

#pragma unroll
    for (int j = 0; j < 4; j++) cp16(smem_u32(As + aoff[j]), asrc[j], aval[j]);
#pragma unroll
    for (int j = 0; j < 4; j++) cp16(smem_u32(Bs + boff[j]), bptr[j], true);
    cp_commit();

    const int NIT = I / BK;   // 64
    for (int it = 0; it < NIT; ++it) {
        if (it + 1 < NIT) {
            int k0 = (it + 1) * BK;
            int sa = ((it + 1) & 1) ? BM * ASTR : 0;
            int sb = ((it + 1) & 1) ? BK * BSTR : 0;
#pragma unroll
            for (int j = 0; j < 4; j++)
                cp16(smem_u32(As + sa + aoff[j]), asrc[j] + k0, aval[j]);
#pragma unroll
            for (int j = 0; j < 4; j++)
                cp16(smem_u32(Bs + sb + boff[j]), bptr[j] + (size_t)k0 * H, true);
        }
        cp_commit();
        cp_wait1();
        __syncthreads();
        const float* Asl = As + ((it & 1) ? BM * ASTR : 0);
        const float* Bsl = Bs + ((it & 1) ? BK * BSTR : 0);
#pragma unroll
        for (int ks = 0; ks < 4; ks++) {
            uint32_t a[4][4];
#pragma unroll
            for (int mt = 0; mt < 4; mt++) {
                int mr = wm * 64 + mt * 16;
                a[mt][0] = __float_as_uint(Asl[(mr + r    ) * ASTR + ks * 8 + c    ]);
                a[mt][1] = __float_as_uint(Asl[(mr + r + 8) * ASTR + ks * 8 + c    ]);
                a[mt][2] = __float_as_uint(Asl[(mr + r    ) * ASTR + ks * 8 + c + 4]);
                a[mt][3] = __float_as_uint(Asl[(mr + r + 8) * ASTR + ks * 8 + c + 4]);
            }
#pragma unroll
            for (int nt = 0; nt < 4; nt++) {
                int nc = wn * 32 + nt * 8 + r;
                uint32_t b[2];
                b[0] = __float_as_uint(Bsl[(ks * 8 + c    ) * BSTR + nc]);
                b[1] = __float_as_uint(Bsl[(ks * 8 + c + 4) * BSTR + nc]);
#pragma unroll
                for (int mt = 0; mt < 4; mt++)
                    mma_tf32(acc[mt][nt], a[mt], b);
            }
        }
        __syncthreads();
    }

#pragma unroll
    for (int mt = 0; mt < 4; mt++) {
#pragma unroll
        for (int hrow = 0; hrow < 2; hrow++) {
            int rr = m0 + wm * 64 + mt * 16 + r + hrow * 8;
            if (rr >= cnt) continue;
            int token = shm ? rr : g_tok[e][rr];
            float w = shm ? 1.0f : g_wt[e][rr];
            float* dst = routed + (size_t)token * H;
#pragma unroll
            for (int nt = 0; nt < 4; nt++) {
                int col = n0 + wn * 32 + nt * 8 + 2 * c;
                atomicAdd(dst + col + 0, w * acc[mt][nt][hrow * 2 + 0]);
                atomicAdd(dst + col + 1, w * acc[mt][nt][hrow * 2 + 1]);
            }
        }
    }
}

// ---------------- finalize losses ----------------
__global__ void finalize_kernel(float* __restrict__ out) {
    int tid = threadIdx.x;
    float ps[E];
#pragma unroll
    for (int e = 0; e < E; e++) ps[e] = 0.0f;
    float zs = 0.0f;
    for (int t = tid; t < T; t += 256) {
        zs += g_z[t];
#pragma unroll
        for (int e = 0; e < E; e++) ps[e] += g_probs[(size_t)t * E + e];
    }
#pragma unroll
    for (int off = 16; off > 0; off >>= 1) {
        zs += __shfl_down_sync(0xFFFFFFFFu, zs, off);
#pragma unroll
        for (int e = 0; e < E; e++)
            ps[e] += __shfl_down_sync(0xFFFFFFFFu, ps[e], off);
    }
    __shared__ float sp[8][E];
    __shared__ float sz[8];
    int warp = tid >> 5, lane = tid & 31;
    if (lane == 0) {
        sz[warp] = zs;
#pragma unroll
        for (int e = 0; e < E; e++) sp[warp][e] = ps[e];
    }
    __syncthreads();
    if (tid == 0) {
        float ztot = 0.0f, ptot[E];
#pragma unroll
        for (int e = 0; e < E; e++) ptot[e] = 0.0f;
#pragma unroll
        for (int w = 0; w < 8; w++) {
            ztot += sz[w];
#pragma unroll
            for (int e = 0; e < E; e++) ptot[e] += sp[w][e];
        }
        float aux = 0.0f;
#pragma unroll
        for (int e = 0; e < E; e++) {
            float tpe = 0.5f * (float)g_count[e] / (float)T;
            float ppe = ptot[e] / (float)T;
            aux += tpe * ppe;
        }
        out[OUT_AUX] = (float)E * aux;
        out[OUT_Z]   = ztot / (float)T;
    }
}

// ---------------- launch ----------------
extern "C" void kernel_launch(void* const* d_in, const int* in_sizes, int n_in,
                              void* d_out, int out_size) {
    const float* x  = (const float*)d_in[0];
    const float* rw = (const float*)d_in[1];
    const float* gw = (const float*)d_in[2];
    const float* uw = (const float*)d_in[3];
    const float* dw = (const float*)d_in[4];
    const float* sg = (const float*)d_in[5];
    const float* su = (const float*)d_in[6];
    const float* sd = (const float*)d_in[7];
    float* out = (float*)d_out;

    cudaFuncSetAttribute(gemm1_kernel, cudaFuncAttributeMaxDynamicSharedMemorySize, SMEMG);
    cudaFuncSetAttribute(gemm2_kernel, cudaFuncAttributeMaxDynamicSharedMemorySize, SMEMG);

    float* xr;  cudaGetSymbolAddress((void**)&xr,  g_xr);
    float* gwr; cudaGetSymbolAddress((void**)&gwr, g_gwr);
    float* uwr; cudaGetSymbolAddress((void**)&uwr, g_uwr);
    float* dwr; cudaGetSymbolAddress((void**)&dwr, g_dwr);
    float* sgr; cudaGetSymbolAddress((void**)&sgr, g_sgr);
    float* sur; cudaGetSymbolAddress((void**)&sur, g_sur);
    float* sdr; cudaGetSymbolAddress((void**)&sdr, g_sdr);

    // prep: tf32 pre-rounding
    round_kernel<<<(T * H / 4 + 255) / 256, 256>>>(x, xr, T * H / 4);
    round_kernel<<<(E * H * I / 4 + 255) / 256, 256>>>(gw, gwr, E * H * I / 4);
    round_kernel<<<(E * H * I / 4 + 255) / 256, 256>>>(uw, uwr, E * H * I / 4);
    round_kernel<<<(E * I * H / 4 + 255) / 256, 256>>>(dw, dwr, E * I * H / 4);
    round_kernel<<<(H * I / 4 + 255) / 256, 256>>>(sg, sgr, H * I / 4);
    round_kernel<<<(H * I / 4 + 255) / 256, 256>>>(su, sur, H * I / 4);
    round_kernel<<<(I * H / 4 + 255) / 256, 256>>>(sd, sdr, I * H / 4);

    init_kernel<<<1, 32>>>();
    zero_routed<<<T * H / 4 / 256, 256>>>(out);
    router_kernel<<<T, 256>>>(x, rw, out + OUT_LOG);

    gemm1_kernel<<<dim3(2 * I / BN, T / BM, E + 1), 256, SMEMG>>>();
    swiglu_kernel<<<dim3(I / 1024, T, E + 1), 256>>>();
    gemm2_kernel<<<dim3(H / BN, T / BM, E + 1), 256, SMEMG>>>(out);

    finalize_kernel<<<1, 256>>>(out);
}

// round 11
// speedup vs baseline: 1.5187x; 1.4660x over previous
#include <cuda_runtime.h>
#include <cuda_bf16.h>
#include <cstdint>
#include <math.h>

#define H 1024
#define I 2048
#define E 8
#define T 4096

// out layout: [0, T*H) routed ; [T*H] aux ; [T*H+1] z ; [T*H+2, +T*E) logits
#define OUT_AUX   (T*H)
#define OUT_Z     (T*H + 1)
#define OUT_LOG   (T*H + 2)

// GEMM tiling (R5-proven)
#define BM 128
#define BN 64
#define BK 32
#define ASTR 36     // A smem row stride (floats)
#define BSTR 72     // B smem row stride (floats)

// ---------------- device scratch (allocation-free contract) ----------------
__device__ int   g_count[E];
__device__ int   g_tok[E][T];
__device__ float g_wt[E][T];
__device__ float g_probs[T * E];
__device__ float g_z[T];
__device__ float g_inter[(size_t)E * T * I];     // tf32-rounded SwiGLU intermediate
__device__ float g_sinter[(size_t)T * I];        // shared-expert intermediate
__device__ float g_xr [(size_t)T * H];           // tf32-rounded x
__device__ float g_gwr[(size_t)E * H * I];       // tf32-rounded weights
__device__ float g_uwr[(size_t)E * H * I];
__device__ float g_dwr[(size_t)E * I * H];
__device__ float g_sgr[(size_t)H * I];
__device__ float g_sur[(size_t)H * I];
__device__ float g_sdr[(size_t)I * H];

__device__ __forceinline__ float silu(float v) { return v / (1.0f + expf(-v)); }

__device__ __forceinline__ uint32_t tf32bits(float f) {
    uint32_t r; asm("cvt.rna.tf32.f32 %0, %1;\n" : "=r"(r) : "f"(f)); return r;
}
__device__ __forceinline__ uint32_t smem_u32(const void* p) {
    return (uint32_t)__cvta_generic_to_shared(p);
}
__device__ __forceinline__ void cp16(uint32_t dst, const void* src, bool pred) {
    int sz = pred ? 16 : 0;
    asm volatile("cp.async.cg.shared.global [%0], [%1], 16, %2;\n"
                 :: "r"(dst), "l"(src), "r"(sz));
}
__device__ __forceinline__ void cp_commit() { asm volatile("cp.async.commit_group;\n"); }
__device__ __forceinline__ void cp_wait1()  { asm volatile("cp.async.wait_group 1;\n"); }

__device__ __forceinline__ void mma_tf32(float* c, const uint32_t* a, const uint32_t* b) {
    asm volatile("mma.sync.aligned.m16n8k8.row.col.f32.tf32.tf32.f32 "
                 "{%0,%1,%2,%3}, {%4,%5,%6,%7}, {%8,%9}, {%0,%1,%2,%3};\n"
                 : "+f"(c[0]), "+f"(c[1]), "+f"(c[2]), "+f"(c[3])
                 : "r"(a[0]), "r"(a[1]), "r"(a[2]), "r"(a[3]),
                   "r"(b[0]), "r"(b[1]));
}

// ---------------- prep: tf32 rounding (weights only) ----------------
__global__ void round_kernel(const float* __restrict__ src, float* __restrict__ dst, int n4) {
    int i = blockIdx.x * blockDim.x + threadIdx.x;
    if (i >= n4) return;
    float4 v = reinterpret_cast<const float4*>(src)[i];
    v.x = __uint_as_float(tf32bits(v.x));
    v.y = __uint_as_float(tf32bits(v.y));
    v.z = __uint_as_float(tf32bits(v.z));
    v.w = __uint_as_float(tf32bits(v.w));
    reinterpret_cast<float4*>(dst)[i] = v;
}

// ---------------- init ----------------
__global__ void init_kernel() {
    int i = threadIdx.x;
    if (i < E) g_count[i] = 0;
}

// ---------------- router (+ fused x tf32-round) ----------------
__global__ void router_kernel(const float* __restrict__ x,
                              const float* __restrict__ rw,
                              float* __restrict__ out_logits) {
    int t = blockIdx.x;
    int tid = threadIdx.x;
    const float* xr = x + (size_t)t * H;

    float p[E];
#pragma unroll
    for (int e = 0; e < E; e++) p[e] = 0.0f;
    for (int h = tid; h < H; h += 256) {
        float xv = xr[h];
        g_xr[(size_t)t * H + h] = __uint_as_float(tf32bits(xv));
        const float* r = rw + (size_t)h * E;
#pragma unroll
        for (int e = 0; e < E; e++) p[e] += xv * r[e];
    }
#pragma unroll
    for (int off = 16; off > 0; off >>= 1)
#pragma unroll
        for (int e = 0; e < E; e++)
            p[e] += __shfl_down_sync(0xFFFFFFFFu, p[e], off);

    __shared__ float sred[8][E];
    int warp = tid >> 5, lane = tid & 31;
    if (lane == 0)
#pragma unroll
        for (int e = 0; e < E; e++) sred[warp][e] = p[e];
    __syncthreads();

    if (tid == 0) {
        float logit[E];
#pragma unroll
        for (int e = 0; e < E; e++) {
            float s = 0.0f;
#pragma unroll
            for (int w = 0; w < 8; w++) s += sred[w][e];
            logit[e] = s;
            out_logits[(size_t)t * E + e] = s;
        }
        float mx = logit[0];
#pragma unroll
        for (int e = 1; e < E; e++) mx = fmaxf(mx, logit[e]);
        float se = 0.0f, pr[E];
#pragma unroll
        for (int e = 0; e < E; e++) { pr[e] = expf(logit[e] - mx); se += pr[e]; }
        float inv = 1.0f / se;
#pragma unroll
        for (int e = 0; e < E; e++) { pr[e] *= inv; g_probs[(size_t)t * E + e] = pr[e]; }
        float lse = mx + logf(se);
        g_z[t] = lse * lse;

        int i0 = 0;
#pragma unroll
        for (int e = 1; e < E; e++) if (pr[e] > pr[i0]) i0 = e;
        int i1 = (i0 == 0) ? 1 : 0;
#pragma unroll
        for (int e = 0; e < E; e++) if (e != i0 && pr[e] > pr[i1]) i1 = e;

        float w0 = pr[i0], w1 = pr[i1];
        float ws = 1.0f / (w0 + w1);
        w0 *= ws; w1 *= ws;
        int s0 = atomicAdd(&g_count[i0], 1);
        g_tok[i0][s0] = t; g_wt[i0][s0] = w0;
        int s1 = atomicAdd(&g_count[i1], 1);
        g_tok[i1][s1] = t; g_wt[i1][s1] = w1;
    }
}

// ---------------- GEMM1: inter = tf32(silu(X@G) * (X@U)) ----------------
// grid (I/64, T/128, E+1); z==E -> shared expert (writes g_sinter)
__global__ void __launch_bounds__(256, 2)
gemm1_kernel() {
    extern __shared__ float sm[];
    float* As = sm;                                  // 2 * BM * ASTR
    float* Bg = As + 2 * BM * ASTR;                  // 2 * BK * BSTR
    float* Bu = Bg + 2 * BK * BSTR;

    int z = blockIdx.z;
    bool shm = (z == E);
    int e   = shm ? 0 : z;
    int cnt = shm ? T : g_count[e];
    int m0  = blockIdx.y * BM;
    if (m0 >= cnt) return;
    int n0 = blockIdx.x * BN;

    const float* gsrc = shm ? g_sgr : (g_gwr + (size_t)e * H * I);
    const float* usrc = shm ? g_sur : (g_uwr + (size_t)e * H * I);
    float* ibase = shm ? g_sinter : (g_inter + (size_t)e * T * I);

    int tid = threadIdx.x;
    int lane = tid & 31, warp = tid >> 5;
    int wm = warp & 3, wn = warp >> 2;
    int r = lane >> 2, c = lane & 3;

    // A loads: 4x 16B chunks/thread; rows fixed across k-iters
    const float* asrc[4]; bool aval[4]; uint32_t aoff[4];
#pragma unroll
    for (int j = 0; j < 4; j++) {
        int item = tid + j * 256;
        int arow = item >> 3, achk = item & 7;
        int rr = m0 + arow;
        bool v = rr < cnt;
        int token = shm ? rr : (v ? g_tok[e][rr] : 0);
        asrc[j] = g_xr + (size_t)token * H + achk * 4;
        aval[j] = v;
        aoff[j] = (uint32_t)(arow * ASTR + achk * 4);
    }
    // B loads: 2x 16B chunks/thread per matrix
    const float* gptr[2]; const float* uptr[2]; uint32_t boff[2];
#pragma unroll
    for (int j = 0; j < 2; j++) {
        int item = tid + j * 256;
        int brow = item >> 4, bchk = item & 15;
        gptr[j] = gsrc + (size_t)brow * I + n0 + bchk * 4;
        uptr[j] = usrc + (size_t)brow * I + n0 + bchk * 4;
        boff[j] = (uint32_t)(brow * BSTR + bchk * 4);
    }

    float accG[2][4][4] = {}, accU[2][4][4] = {};

    // prologue: stage 0
#pragma unroll
    for (int j = 0; j < 4; j++) cp16(smem_u32(As + aoff[j]), asrc[j], aval[j]);
#pragma unroll
    for (int j = 0; j < 2; j++) {
        cp16(smem_u32(Bg + boff[j]), gptr[j], true);
        cp16(smem_u32(Bu + boff[j]), uptr[j], true);
    }
    cp_commit();

    const int NIT = H / BK;   // 32
    for (int it = 0; it < NIT; ++it) {
        if (it + 1 < NIT) {
            int k0 = (it + 1) * BK;
            int so = ((it + 1) & 1) ? BM * ASTR : 0;
            int sb = ((it + 1) & 1) ? BK * BSTR : 0;
#pragma unroll
            for (int j = 0; j < 4; j++)
                cp16(smem_u32(As + so + aoff[j]), asrc[j] + k0, aval[j]);
#pragma unroll
            for (int j = 0; j < 2; j++) {
                cp16(smem_u32(Bg + sb + boff[j]), gptr[j] + (size_t)k0 * I, true);
                cp16(smem_u32(Bu + sb + boff[j]), uptr[j] + (size_t)k0 * I, true);
            }
        }
        cp_commit();
        cp_wait1();
        __syncthreads();
        const float* Asl = As + ((it & 1) ? BM * ASTR : 0);
        const float* Bgl = Bg + ((it & 1) ? BK * BSTR : 0);
        const float* Bul = Bu + ((it & 1) ? BK * BSTR : 0);
#pragma unroll
        for (int ks = 0; ks < 4; ks++) {
            uint32_t a[2][4];
#pragma unroll
            for (int mt = 0; mt < 2; mt++) {
                int mr = wm * 32 + mt * 16;
                a[mt][0] = __float_as_uint(Asl[(mr + r    ) * ASTR + ks * 8 + c    ]);
                a[mt][1] = __float_as_uint(Asl[(mr + r + 8) * ASTR + ks * 8 + c    ]);
                a[mt][2] = __float_as_uint(Asl[(mr + r    ) * ASTR + ks * 8 + c + 4]);
                a[mt][3] = __float_as_uint(Asl[(mr + r + 8) * ASTR + ks * 8 + c + 4]);
            }
#pragma unroll
            for (int nt = 0; nt < 4; nt++) {
                int nc = wn * 32 + nt * 8 + r;
                uint32_t bg[2], bu[2];
                bg[0] = __float_as_uint(Bgl[(ks * 8 + c    ) * BSTR + nc]);
                bg[1] = __float_as_uint(Bgl[(ks * 8 + c + 4) * BSTR + nc]);
                bu[0] = __float_as_uint(Bul[(ks * 8 + c    ) * BSTR + nc]);
                bu[1] = __float_as_uint(Bul[(ks * 8 + c + 4) * BSTR + nc]);
#pragma unroll
                for (int mt = 0; mt < 2; mt++) {
                    mma_tf32(accG[mt][nt], a[mt], bg);
                    mma_tf32(accU[mt][nt], a[mt], bu);
                }
            }
        }
        __syncthreads();
    }

    // epilogue: tf32-rounded silu(g)*u
#pragma unroll
    for (int mt = 0; mt < 2; mt++) {
#pragma unroll
        for (int hrow = 0; hrow < 2; hrow++) {
            int rr = m0 + wm * 32 + mt * 16 + r + hrow * 8;
            if (rr >= cnt) continue;
#pragma unroll
            for (int nt = 0; nt < 4; nt++) {
                int col = n0 + wn * 32 + nt * 8 + 2 * c;
                float g0 = accG[mt][nt][hrow * 2 + 0];
                float g1 = accG[mt][nt][hrow * 2 + 1];
                float u0 = accU[mt][nt][hrow * 2 + 0];
                float u1 = accU[mt][nt][hrow * 2 + 1];
                float2 o;
                o.x = __uint_as_float(tf32bits(silu(g0) * u0));
                o.y = __uint_as_float(tf32bits(silu(g1) * u1));
                *reinterpret_cast<float2*>(ibase + (size_t)rr * I + col) = o;
            }
        }
    }
}

// ---------------- GEMM2: routed (+)= w * (inter @ D) ----------------
// shared_mode=1: grid (H/64, T/128, 1), plain store (first writer)
// shared_mode=0: grid (H/64, T/128, E), weighted atomicAdd
__global__ void __launch_bounds__(256, 2)
gemm2_kernel(float* __restrict__ routed, int shared_mode) {
    extern __shared__ float sm[];
    float* As = sm;
    float* Bd = As + 2 * BM * ASTR;

    bool shm = (shared_mode != 0);
    int e   = shm ? 0 : blockIdx.z;
    int cnt = shm ? T : g_count[e];
    int m0  = blockIdx.y * BM;
    if (m0 >= cnt) return;
    int n0 = blockIdx.x * BN;

    const float* dsrc = shm ? g_sdr : (g_dwr + (size_t)e * I * H);
    const float* inter = shm ? g_sinter : (g_inter + (size_t)e * T * I);

    int tid = threadIdx.x;
    int lane = tid & 31, warp = tid >> 5;
    int wm = warp & 3, wn = warp >> 2;
    int r = lane >> 2, c = lane & 3;

    const float* asrc[4]; bool aval[4]; uint32_t aoff[4];
#pragma unroll
    for (int j = 0; j < 4; j++) {
        int item = tid + j * 256;
        int arow = item >> 3, achk = item & 7;
        int rr = m0 + arow;
        bool v = rr < cnt;
        asrc[j] = inter + (size_t)(v ? rr : 0) * I + achk * 4;
        aval[j] = v;
        aoff[j] = (uint32_t)(arow * ASTR + achk * 4);
    }
    const float* dptr[2]; uint32_t boff[2];
#pragma unroll
    for (int j = 0; j < 2; j++) {
        int item = tid + j * 256;
        int brow = item >> 4, bchk = item & 15;
        dptr[j] = dsrc + (size_t)brow * H + n0 + bchk * 4;
        boff[j] = (uint32_t)(brow * BSTR + bchk * 4);
    }

    float acc[2][4][4] = {};

#pragma unroll
    for (int j = 0; j < 4; j++) cp16(smem_u32(As + aoff[j]), asrc[j], aval[j]);
#pragma unroll
    for (int j = 0; j < 2; j++) cp16(smem_u32(Bd + boff[j]), dptr[j], true);
    cp_commit();

    const int NIT = I / BK;   // 64
    for (int it = 0; it < NIT; ++it) {
        if (it + 1 < NIT) {
            int k0 = (it + 1) * BK;
            int so = ((it + 1) & 1) ? BM * ASTR : 0;
            int sb = ((it + 1) & 1) ? BK * BSTR : 0;
#pragma unroll
            for (int j = 0; j < 4; j++)
                cp16(smem_u32(As + so + aoff[j]), asrc[j] + k0, aval[j]);
#pragma unroll
            for (int j = 0; j < 2; j++)
                cp16(smem_u32(Bd + sb + boff[j]), dptr[j] + (size_t)k0 * H, true);
        }
        cp_commit();
        cp_wait1();
        __syncthreads();
        const float* Asl = As + ((it & 1) ? BM * ASTR : 0);
        const float* Bdl = Bd + ((it & 1) ? BK * BSTR : 0);
#pragma unroll
        for (int ks = 0; ks < 4; ks++) {
            uint32_t a[2][4];
#pragma unroll
            for (int mt = 0; mt < 2; mt++) {
                int mr = wm * 32 + mt * 16;
                a[mt][0] = __float_as_uint(Asl[(mr + r    ) * ASTR + ks * 8 + c    ]);
                a[mt][1] = __float_as_uint(Asl[(mr + r + 8) * ASTR + ks * 8 + c    ]);
                a[mt][2] = __float_as_uint(Asl[(mr + r    ) * ASTR + ks * 8 + c + 4]);
                a[mt][3] = __float_as_uint(Asl[(mr + r + 8) * ASTR + ks * 8 + c + 4]);
            }
#pragma unroll
            for (int nt = 0; nt < 4; nt++) {
                int nc = wn * 32 + nt * 8 + r;
                uint32_t bb[2];
                bb[0] = __float_as_uint(Bdl[(ks * 8 + c    ) * BSTR + nc]);
                bb[1] = __float_as_uint(Bdl[(ks * 8 + c + 4) * BSTR + nc]);
#pragma unroll
                for (int mt = 0; mt < 2; mt++)
                    mma_tf32(acc[mt][nt], a[mt], bb);
            }
        }
        __syncthreads();
    }

#pragma unroll
    for (int mt = 0; mt < 2; mt++) {
#pragma unroll
        for (int hrow = 0; hrow < 2; hrow++) {
            int rr = m0 + wm * 32 + mt * 16 + r + hrow * 8;
            if (rr >= cnt) continue;
            if (shm) {
#pragma unroll
                for (int nt = 0; nt < 4; nt++) {
                    int col = n0 + wn * 32 + nt * 8 + 2 * c;
                    float2 o = make_float2(acc[mt][nt][hrow * 2 + 0],
                                           acc[mt][nt][hrow * 2 + 1]);
                    *reinterpret_cast<float2*>(routed + (size_t)rr * H + col) = o;
                }
            } else {
                int token = g_tok[e][rr];
                float w = g_wt[e][rr];
                float* dst = routed + (size_t)token * H;
#pragma unroll
                for (int nt = 0; nt < 4; nt++) {
                    int col = n0 + wn * 32 + nt * 8 + 2 * c;
                    atomicAdd(dst + col + 0, w * acc[mt][nt][hrow * 2 + 0]);
                    atomicAdd(dst + col + 1, w * acc[mt][nt][hrow * 2 + 1]);
                }
            }
        }
    }
}

// ---------------- finalize losses ----------------
__global__ void finalize_kernel(float* __restrict__ out) {
    int tid = threadIdx.x;
    float ps[E];
#pragma unroll
    for (int e = 0; e < E; e++) ps[e] = 0.0f;
    float zs = 0.0f;
    for (int t = tid; t < T; t += 256) {
        zs += g_z[t];
#pragma unroll
        for (int e = 0; e < E; e++) ps[e] += g_probs[(size_t)t * E + e];
    }
#pragma unroll
    for (int off = 16; off > 0; off >>= 1) {
        zs += __shfl_down_sync(0xFFFFFFFFu, zs, off);
#pragma unroll
        for (int e = 0; e < E; e++)
            ps[e] += __shfl_down_sync(0xFFFFFFFFu, ps[e], off);
    }
    __shared__ float sp[8][E];
    __shared__ float sz[8];
    int warp = tid >> 5, lane = tid & 31;
    if (lane == 0) {
        sz[warp] = zs;
#pragma unroll
        for (int e = 0; e < E; e++) sp[warp][e] = ps[e];
    }
    __syncthreads();
    if (tid == 0) {
        float ztot = 0.0f, ptot[E];
#pragma unroll
        for (int e = 0; e < E; e++) ptot[e] = 0.0f;
#pragma unroll
        for (int w = 0; w < 8; w++) {
            ztot += sz[w];
#pragma unroll
            for (int e = 0; e < E; e++) ptot[e] += sp[w][e];
        }
        float aux = 0.0f;
#pragma unroll
        for (int e = 0; e < E; e++) {
            float tpe = 0.5f * (float)g_count[e] / (float)T;
            float ppe = ptot[e] / (float)T;
            aux += tpe * ppe;
        }
        out[OUT_AUX] = (float)E * aux;
        out[OUT_Z]   = ztot / (float)T;
    }
}

// ---------------- launch ----------------
extern "C" void kernel_launch(void* const* d_in, const int* in_sizes, int n_in,
                              void* d_out, int out_size) {
    const float* x  = (const float*)d_in[0];
    const float* rw = (const float*)d_in[1];
    const float* gw = (const float*)d_in[2];
    const float* uw = (const float*)d_in[3];
    const float* dw = (const float*)d_in[4];
    const float* sg = (const float*)d_in[5];
    const float* su = (const float*)d_in[6];
    const float* sd = (const float*)d_in[7];
    float* out = (float*)d_out;

    const int SMEM1 = (2 * BM * ASTR + 4 * BK * BSTR) * 4;   // 73728
    const int SMEM2 = (2 * BM * ASTR + 2 * BK * BSTR) * 4;   // 55296
    cudaFuncSetAttribute(gemm1_kernel, cudaFuncAttributeMaxDynamicSharedMemorySize, SMEM1);
    cudaFuncSetAttribute(gemm2_kernel, cudaFuncAttributeMaxDynamicSharedMemorySize, SMEM2);

    float* gwr; cudaGetSymbolAddress((void**)&gwr, g_gwr);
    float* uwr; cudaGetSymbolAddress((void**)&uwr, g_uwr);
    float* dwr; cudaGetSymbolAddress((void**)&dwr, g_dwr);
    float* sgr; cudaGetSymbolAddress((void**)&sgr, g_sgr);
    float* sur; cudaGetSymbolAddress((void**)&sur, g_sur);
    float* sdr; cudaGetSymbolAddress((void**)&sdr, g_sdr);

    // prep: tf32 pre-rounding of weights (x rounded inside router)
    round_kernel<<<(E * H * I / 4 + 255) / 256, 256>>>(gw, gwr, E * H * I / 4);
    round_kernel<<<(E * H * I / 4 + 255) / 256, 256>>>(uw, uwr, E * H * I / 4);
    round_kernel<<<(E * I * H / 4 + 255) / 256, 256>>>(dw, dwr, E * I * H / 4);
    round_kernel<<<(H * I / 4 + 255) / 256, 256>>>(sg, sgr, H * I / 4);
    round_kernel<<<(H * I / 4 + 255) / 256, 256>>>(su, sur, H * I / 4);
    round_kernel<<<(I * H / 4 + 255) / 256, 256>>>(sd, sdr, I * H / 4);

    init_kernel<<<1, 32>>>();
    router_kernel<<<T, 256>>>(x, rw, out + OUT_LOG);

    // fused gemm1: experts (z<E) + shared (z==E)
    gemm1_kernel<<<dim3(I / BN, T / BM, E + 1), 256, SMEM1>>>();

    // gemm2: shared expert first (plain store covers all of routed),
    // then experts (weighted atomicAdd on top)
    gemm2_kernel<<<dim3(H / BN, T / BM, 1), 256, SMEM2>>>(out, 1);
    gemm2_kernel<<<dim3(H / BN, T / BM, E), 256, SMEM2>>>(out, 0);

    finalize_kernel<<<1, 256>>>(out);
}

// round 15
// speedup vs baseline: 1.6077x; 1.0586x over previous
#include <cuda_runtime.h>
#include <cuda_bf16.h>
#include <cstdint>
#include <math.h>

#define H 1024
#define I 2048
#define E 8
#define T 4096

// out layout: [0, T*H) routed ; [T*H] aux ; [T*H+1] z ; [T*H+2, +T*E) logits
#define OUT_AUX   (T*H)
#define OUT_Z     (T*H + 1)
#define OUT_LOG   (T*H + 2)

// GEMM tiling (R5-proven)
#define BM 128
#define BN 64
#define BK 32
#define ASTR 36     // A smem row stride (floats)
#define BSTR 72     // B smem row stride (floats)

// ---------------- device scratch (allocation-free contract) ----------------
__device__ int   g_count[E];
__device__ int   g_tok[E][T];
__device__ float g_wt[E][T];
__device__ float g_probs[T * E];
__device__ float g_z[T];
__device__ float g_inter[(size_t)E * T * I];     // tf32-rounded SwiGLU intermediate
__device__ float g_sinter[(size_t)T * I];        // shared-expert intermediate
__device__ float g_xr [(size_t)T * H];           // tf32-rounded x
__device__ float g_gwr[(size_t)E * H * I];       // tf32-rounded weights
__device__ float g_uwr[(size_t)E * H * I];
__device__ float g_dwr[(size_t)E * I * H];
__device__ float g_sgr[(size_t)H * I];
__device__ float g_sur[(size_t)H * I];
__device__ float g_sdr[(size_t)I * H];

__device__ __forceinline__ float silu(float v) { return v / (1.0f + expf(-v)); }

__device__ __forceinline__ uint32_t tf32bits(float f) {
    uint32_t r; asm("cvt.rna.tf32.f32 %0, %1;\n" : "=r"(r) : "f"(f)); return r;
}
__device__ __forceinline__ uint32_t smem_u32(const void* p) {
    return (uint32_t)__cvta_generic_to_shared(p);
}
__device__ __forceinline__ void cp16(uint32_t dst, const void* src, bool pred) {
    int sz = pred ? 16 : 0;
    asm volatile("cp.async.cg.shared.global [%0], [%1], 16, %2;\n"
                 :: "r"(dst), "l"(src), "r"(sz));
}
__device__ __forceinline__ void cp_commit() { asm volatile("cp.async.commit_group;\n"); }
__device__ __forceinline__ void cp_wait1()  { asm volatile("cp.async.wait_group 1;\n"); }

__device__ __forceinline__ void mma_tf32(float* c, const uint32_t* a, const uint32_t* b) {
    asm volatile("mma.sync.aligned.m16n8k8.row.col.f32.tf32.tf32.f32 "
                 "{%0,%1,%2,%3}, {%4,%5,%6,%7}, {%8,%9}, {%0,%1,%2,%3};\n"
                 : "+f"(c[0]), "+f"(c[1]), "+f"(c[2]), "+f"(c[3])
                 : "r"(a[0]), "r"(a[1]), "r"(a[2]), "r"(a[3]),
                   "r"(b[0]), "r"(b[1]));
}

// ---------------- prep: tf32 rounding (weights only) ----------------
__global__ void round_kernel(const float* __restrict__ src, float* __restrict__ dst, int n4) {
    int i = blockIdx.x * blockDim.x + threadIdx.x;
    if (i >= n4) return;
    float4 v = reinterpret_cast<const float4*>(src)[i];
    v.x = __uint_as_float(tf32bits(v.x));
    v.y = __uint_as_float(tf32bits(v.y));
    v.z = __uint_as_float(tf32bits(v.z));
    v.w = __uint_as_float(tf32bits(v.w));
    reinterpret_cast<float4*>(dst)[i] = v;
}

__global__ void zero_routed(float* __restrict__ out) {
    int i = blockIdx.x * blockDim.x + threadIdx.x;
    reinterpret_cast<float4*>(out)[i] = make_float4(0.f, 0.f, 0.f, 0.f);
}

__global__ void init_kernel() {
    int i = threadIdx.x;
    if (i < E) g_count[i] = 0;
}

// ---------------- router (+ fused x tf32-round) ----------------
__global__ void router_kernel(const float* __restrict__ x,
                              const float* __restrict__ rw,
                              float* __restrict__ out_logits) {
    int t = blockIdx.x;
    int tid = threadIdx.x;
    const float* xr = x + (size_t)t * H;

    float p[E];
#pragma unroll
    for (int e = 0; e < E; e++) p[e] = 0.0f;
    for (int h = tid; h < H; h += 256) {
        float xv = xr[h];
        g_xr[(size_t)t * H + h] = __uint_as_float(tf32bits(xv));
        const float* r = rw + (size_t)h * E;
#pragma unroll
        for (int e = 0; e < E; e++) p[e] += xv * r[e];
    }
#pragma unroll
    for (int off = 16; off > 0; off >>= 1)
#pragma unroll
        for (int e = 0; e < E; e++)
            p[e] += __shfl_down_sync(0xFFFFFFFFu, p[e], off);

    __shared__ float sred[8][E];
    int warp = tid >> 5, lane = tid & 31;
    if (lane == 0)
#pragma unroll
        for (int e = 0; e < E; e++) sred[warp][e] = p[e];
    __syncthreads();

    if (tid == 0) {
        float logit[E];
#pragma unroll
        for (int e = 0; e < E; e++) {
            float s = 0.0f;
#pragma unroll
            for (int w = 0; w < 8; w++) s += sred[w][e];
            logit[e] = s;
            out_logits[(size_t)t * E + e] = s;
        }
        float mx = logit[0];
#pragma unroll
        for (int e = 1; e < E; e++) mx = fmaxf(mx, logit[e]);
        float se = 0.0f, pr[E];
#pragma unroll
        for (int e = 0; e < E; e++) { pr[e] = expf(logit[e] - mx); se += pr[e]; }
        float inv = 1.0f / se;
#pragma unroll
        for (int e = 0; e < E; e++) { pr[e] *= inv; g_probs[(size_t)t * E + e] = pr[e]; }
        float lse = mx + logf(se);
        g_z[t] = lse * lse;

        int i0 = 0;
#pragma unroll
        for (int e = 1; e < E; e++) if (pr[e] > pr[i0]) i0 = e;
        int i1 = (i0 == 0) ? 1 : 0;
#pragma unroll
        for (int e = 0; e < E; e++) if (e != i0 && pr[e] > pr[i1]) i1 = e;

        float w0 = pr[i0], w1 = pr[i1];
        float ws = 1.0f / (w0 + w1);
        w0 *= ws; w1 *= ws;
        int s0 = atomicAdd(&g_count[i0], 1);
        g_tok[i0][s0] = t; g_wt[i0][s0] = w0;
        int s1 = atomicAdd(&g_count[i1], 1);
        g_tok[i1][s1] = t; g_wt[i1][s1] = w1;
    }
}

// ---------------- GEMM1: inter = tf32(silu(X@G) * (X@U)) ----------------
// grid (I/64, T/128, E+1); z==E -> shared expert (writes g_sinter)
__global__ void __launch_bounds__(256, 2)
gemm1_kernel() {
    extern __shared__ float sm[];
    float* As = sm;                                  // 2 * BM * ASTR
    float* Bg = As + 2 * BM * ASTR;                  // 2 * BK * BSTR
    float* Bu = Bg + 2 * BK * BSTR;

    int z = blockIdx.z;
    bool shm = (z == E);
    int e   = shm ? 0 : z;
    int cnt = shm ? T : g_count[e];
    int m0  = blockIdx.y * BM;
    if (m0 >= cnt) return;
    int n0 = blockIdx.x * BN;

    const float* gsrc = shm ? g_sgr : (g_gwr + (size_t)e * H * I);
    const float* usrc = shm ? g_sur : (g_uwr + (size_t)e * H * I);
    float* ibase = shm ? g_sinter : (g_inter + (size_t)e * T * I);

    int tid = threadIdx.x;
    int lane = tid & 31, warp = tid >> 5;
    int wm = warp & 3, wn = warp >> 2;
    int r = lane >> 2, c = lane & 3;

    const float* asrc[4]; bool aval[4]; uint32_t aoff[4];
#pragma unroll
    for (int j = 0; j < 4; j++) {
        int item = tid + j * 256;
        int arow = item >> 3, achk = item & 7;
        int rr = m0 + arow;
        bool v = rr < cnt;
        int token = shm ? rr : (v ? g_tok[e][rr] : 0);
        asrc[j] = g_xr + (size_t)token * H + achk * 4;
        aval[j] = v;
        aoff[j] = (uint32_t)(arow * ASTR + achk * 4);
    }
    const float* gptr[2]; const float* uptr[2]; uint32_t boff[2];
#pragma unroll
    for (int j = 0; j < 2; j++) {
        int item = tid + j * 256;
        int brow = item >> 4, bchk = item & 15;
        gptr[j] = gsrc + (size_t)brow * I + n0 + bchk * 4;
        uptr[j] = usrc + (size_t)brow * I + n0 + bchk * 4;
        boff[j] = (uint32_t)(brow * BSTR + bchk * 4);
    }

    float accG[2][4][4] = {}, accU[2][4][4] = {};

#pragma unroll
    for (int j = 0; j < 4; j++) cp16(smem_u32(As + aoff[j]), asrc[j], aval[j]);
#pragma unroll
    for (int j = 0; j < 2; j++) {
        cp16(smem_u32(Bg + boff[j]), gptr[j], true);
        cp16(smem_u32(Bu + boff[j]), uptr[j], true);
    }
    cp_commit();

    const int NIT = H / BK;   // 32
    for (int it = 0; it < NIT; ++it) {
        if (it + 1 < NIT) {
            int k0 = (it + 1) * BK;
            int so = ((it + 1) & 1) ? BM * ASTR : 0;
            int sb = ((it + 1) & 1) ? BK * BSTR : 0;
#pragma unroll
            for (int j = 0; j < 4; j++)
                cp16(smem_u32(As + so + aoff[j]), asrc[j] + k0, aval[j]);
#pragma unroll
            for (int j = 0; j < 2; j++) {
                cp16(smem_u32(Bg + sb + boff[j]), gptr[j] + (size_t)k0 * I, true);
                cp16(smem_u32(Bu + sb + boff[j]), uptr[j] + (size_t)k0 * I, true);
            }
        }
        cp_commit();
        cp_wait1();
        __syncthreads();
        const float* Asl = As + ((it & 1) ? BM * ASTR : 0);
        const float* Bgl = Bg + ((it & 1) ? BK * BSTR : 0);
        const float* Bul = Bu + ((it & 1) ? BK * BSTR : 0);
#pragma unroll
        for (int ks = 0; ks < 4; ks++) {
            uint32_t a[2][4];
#pragma unroll
            for (int mt = 0; mt < 2; mt++) {
                int mr = wm * 32 + mt * 16;
                a[mt][0] = __float_as_uint(Asl[(mr + r    ) * ASTR + ks * 8 + c    ]);
                a[mt][1] = __float_as_uint(Asl[(mr + r + 8) * ASTR + ks * 8 + c    ]);
                a[mt][2] = __float_as_uint(Asl[(mr + r    ) * ASTR + ks * 8 + c + 4]);
                a[mt][3] = __float_as_uint(Asl[(mr + r + 8) * ASTR + ks * 8 + c + 4]);
            }
#pragma unroll
            for (int nt = 0; nt < 4; nt++) {
                int nc = wn * 32 + nt * 8 + r;
                uint32_t bg[2], bu[2];
                bg[0] = __float_as_uint(Bgl[(ks * 8 + c    ) * BSTR + nc]);
                bg[1] = __float_as_uint(Bgl[(ks * 8 + c + 4) * BSTR + nc]);
                bu[0] = __float_as_uint(Bul[(ks * 8 + c    ) * BSTR + nc]);
                bu[1] = __float_as_uint(Bul[(ks * 8 + c + 4) * BSTR + nc]);
#pragma unroll
                for (int mt = 0; mt < 2; mt++) {
                    mma_tf32(accG[mt][nt], a[mt], bg);
                    mma_tf32(accU[mt][nt], a[mt], bu);
                }
            }
        }
        __syncthreads();
    }

#pragma unroll
    for (int mt = 0; mt < 2; mt++) {
#pragma unroll
        for (int hrow = 0; hrow < 2; hrow++) {
            int rr = m0 + wm * 32 + mt * 16 + r + hrow * 8;
            if (rr >= cnt) continue;
#pragma unroll
            for (int nt = 0; nt < 4; nt++) {
                int col = n0 + wn * 32 + nt * 8 + 2 * c;
                float g0 = accG[mt][nt][hrow * 2 + 0];
                float g1 = accG[mt][nt][hrow * 2 + 1];
                float u0 = accU[mt][nt][hrow * 2 + 0];
                float u1 = accU[mt][nt][hrow * 2 + 1];
                float2 o;
                o.x = __uint_as_float(tf32bits(silu(g0) * u0));
                o.y = __uint_as_float(tf32bits(silu(g1) * u1));
                *reinterpret_cast<float2*>(ibase + (size_t)rr * I + col) = o;
            }
        }
    }
}

// ---------------- GEMM2: routed += w * (inter @ D), fused E+1 ----------
// grid (H/64, T/128, E+1); z==E -> shared (w=1). 3 CTAs/SM for occupancy.
__global__ void __launch_bounds__(256, 3)
gemm2_kernel(float* __restrict__ routed) {
    extern __shared__ float sm[];
    float* As = sm;
    float* Bd = As + 2 * BM * ASTR;

    int z = blockIdx.z;
    bool shm = (z == E);
    int e   = shm ? 0 : z;
    int cnt = shm ? T : g_count[e];
    int m0  = blockIdx.y * BM;
    if (m0 >= cnt) return;
    int n0 = blockIdx.x * BN;

    const float* dsrc = shm ? g_sdr : (g_dwr + (size_t)e * I * H);
    const float* inter = shm ? g_sinter : (g_inter + (size_t)e * T * I);

    int tid = threadIdx.x;
    int lane = tid & 31, warp = tid >> 5;
    int wm = warp & 3, wn = warp >> 2;
    int r = lane >> 2, c = lane & 3;

    const float* asrc[4]; bool aval[4]; uint32_t aoff[4];
#pragma unroll
    for (int j = 0; j < 4; j++) {
        int item = tid + j * 256;
        int arow = item >> 3, achk = item & 7;
        int rr = m0 + arow;
        bool v = rr < cnt;
        asrc[j] = inter + (size_t)(v ? rr : 0) * I + achk * 4;
        aval[j] = v;
        aoff[j] = (uint32_t)(arow * ASTR + achk * 4);
    }
    const float* dptr[2]; uint32_t boff[2];
#pragma unroll
    for (int j = 0; j < 2; j++) {
        int item = tid + j * 256;
        int brow = item >> 4, bchk = item & 15;
        dptr[j] = dsrc + (size_t)brow * H + n0 + bchk * 4;
        boff[j] = (uint32_t)(brow * BSTR + bchk * 4);
    }

    float acc[2][4][4] = {};

#pragma unroll
    for (int j = 0; j < 4; j++) cp16(smem_u32(As + aoff[j]), asrc[j], aval[j]);
#pragma unroll
    for (int j = 0; j < 2; j++) cp16(smem_u32(Bd + boff[j]), dptr[j], true);
    cp_commit();

    const int NIT = I / BK;   // 64
    for (int it = 0; it < NIT; ++it) {
        if (it + 1 < NIT) {
            int k0 = (it + 1) * BK;
            int so = ((it + 1) & 1) ? BM * ASTR : 0;
            int sb = ((it + 1) & 1) ? BK * BSTR : 0;
#pragma unroll
            for (int j = 0; j < 4; j++)
                cp16(smem_u32(As + so + aoff[j]), asrc[j] + k0, aval[j]);
#pragma unroll
            for (int j = 0; j < 2; j++)
                cp16(smem_u32(Bd + sb + boff[j]), dptr[j] + (size_t)k0 * H, true);
        }
        cp_commit();
        cp_wait1();
        __syncthreads();
        const float* Asl = As + ((it & 1) ? BM * ASTR : 0);
        const float* Bdl = Bd + ((it & 1) ? BK * BSTR : 0);
#pragma unroll
        for (int ks = 0; ks < 4; ks++) {
            uint32_t a[2][4];
#pragma unroll
            for (int mt = 0; mt < 2; mt++) {
                int mr = wm * 32 + mt * 16;
                a[mt][0] = __float_as_uint(Asl[(mr + r    ) * ASTR + ks * 8 + c    ]);
                a[mt][1] = __float_as_uint(Asl[(mr + r + 8) * ASTR + ks * 8 + c    ]);
                a[mt][2] = __float_as_uint(Asl[(mr + r    ) * ASTR + ks * 8 + c + 4]);
                a[mt][3] = __float_as_uint(Asl[(mr + r + 8) * ASTR + ks * 8 + c + 4]);
            }
#pragma unroll
            for (int nt = 0; nt < 4; nt++) {
                int nc = wn * 32 + nt * 8 + r;
                uint32_t bb[2];
                bb[0] = __float_as_uint(Bdl[(ks * 8 + c    ) * BSTR + nc]);
                bb[1] = __float_as_uint(Bdl[(ks * 8 + c + 4) * BSTR + nc]);
#pragma unroll
                for (int mt = 0; mt < 2; mt++)
                    mma_tf32(acc[mt][nt], a[mt], bb);
            }
        }
        __syncthreads();
    }

#pragma unroll
    for (int mt = 0; mt < 2; mt++) {
#pragma unroll
        for (int hrow = 0; hrow < 2; hrow++) {
            int rr = m0 + wm * 32 + mt * 16 + r + hrow * 8;
            if (rr >= cnt) continue;
            int token = shm ? rr : g_tok[e][rr];
            float w = shm ? 1.0f : g_wt[e][rr];
            float* dst = routed + (size_t)token * H;
#pragma unroll
            for (int nt = 0; nt < 4; nt++) {
                int col = n0 + wn * 32 + nt * 8 + 2 * c;
                atomicAdd(dst + col + 0, w * acc[mt][nt][hrow * 2 + 0]);
                atomicAdd(dst + col + 1, w * acc[mt][nt][hrow * 2 + 1]);
            }
        }
    }
}

// ---------------- finalize losses ----------------
__global__ void finalize_kernel(float* __restrict__ out) {
    int tid = threadIdx.x;
    float ps[E];
#pragma unroll
    for (int e = 0; e < E; e++) ps[e] = 0.0f;
    float zs = 0.0f;
    for (int t = tid; t < T; t += 256) {
        zs += g_z[t];
#pragma unroll
        for (int e = 0; e < E; e++) ps[e] += g_probs[(size_t)t * E + e];
    }
#pragma unroll
    for (int off = 16; off > 0; off >>= 1) {
        zs += __shfl_down_sync(0xFFFFFFFFu, zs, off);
#pragma unroll
        for (int e = 0; e < E; e++)
            ps[e] += __shfl_down_sync(0xFFFFFFFFu, ps[e], off);
    }
    __shared__ float sp[8][E];
    __shared__ float sz[8];
    int warp = tid >> 5, lane = tid & 31;
    if (lane == 0) {
        sz[warp] = zs;
#pragma unroll
        for (int e = 0; e < E; e++) sp[warp][e] = ps[e];
    }
    __syncthreads();
    if (tid == 0) {
        float ztot = 0.0f, ptot[E];
#pragma unroll
        for (int e = 0; e < E; e++) ptot[e] = 0.0f;
#pragma unroll
        for (int w = 0; w < 8; w++) {
            ztot += sz[w];
#pragma unroll
            for (int e = 0; e < E; e++) ptot[e] += sp[w][e];
        }
        float aux = 0.0f;
#pragma unroll
        for (int e = 0; e < E; e++) {
            float tpe = 0.5f * (float)g_count[e] / (float)T;
            float ppe = ptot[e] / (float)T;
            aux += tpe * ppe;
        }
        out[OUT_AUX] = (float)E * aux;
        out[OUT_Z]   = ztot / (float)T;
    }
}

// ---------------- launch ----------------
extern "C" void kernel_launch(void* const* d_in, const int* in_sizes, int n_in,
                              void* d_out, int out_size) {
    const float* x  = (const float*)d_in[0];
    const float* rw = (const float*)d_in[1];
    const float* gw = (const float*)d_in[2];
    const float* uw = (const float*)d_in[3];
    const float* dw = (const float*)d_in[4];
    const float* sg = (const float*)d_in[5];
    const float* su = (const float*)d_in[6];
    const float* sd = (const float*)d_in[7];
    float* out = (float*)d_out;

    const int SMEM1 = (2 * BM * ASTR + 4 * BK * BSTR) * 4;   // 73728
    const int SMEM2 = (2 * BM * ASTR + 2 * BK * BSTR) * 4;   // 55296
    cudaFuncSetAttribute(gemm1_kernel, cudaFuncAttributeMaxDynamicSharedMemorySize, SMEM1);
    cudaFuncSetAttribute(gemm2_kernel, cudaFuncAttributeMaxDynamicSharedMemorySize, SMEM2);

    float* gwr; cudaGetSymbolAddress((void**)&gwr, g_gwr);
    float* uwr; cudaGetSymbolAddress((void**)&uwr, g_uwr);
    float* dwr; cudaGetSymbolAddress((void**)&dwr, g_dwr);
    float* sgr; cudaGetSymbolAddress((void**)&sgr, g_sgr);
    float* sur; cudaGetSymbolAddress((void**)&sur, g_sur);
    float* sdr; cudaGetSymbolAddress((void**)&sdr, g_sdr);

    // prep: tf32 pre-rounding of weights (x rounded inside router)
    round_kernel<<<(E * H * I / 4 + 255) / 256, 256>>>(gw, gwr, E * H * I / 4);
    round_kernel<<<(E * H * I / 4 + 255) / 256, 256>>>(uw, uwr, E * H * I / 4);
    round_kernel<<<(E * I * H / 4 + 255) / 256, 256>>>(dw, dwr, E * I * H / 4);
    round_kernel<<<(H * I / 4 + 255) / 256, 256>>>(sg, sgr, H * I / 4);
    round_kernel<<<(H * I / 4 + 255) / 256, 256>>>(su, sur, H * I / 4);
    round_kernel<<<(I * H / 4 + 255) / 256, 256>>>(sd, sdr, I * H / 4);

    init_kernel<<<1, 32>>>();
    zero_routed<<<T * H / 4 / 256, 256>>>(out);
    router_kernel<<<T, 256>>>(x, rw, out + OUT_LOG);

    // fused: experts (z<E) + shared (z==E) in one launch each (R5 structure)
    gemm1_kernel<<<dim3(I / BN, T / BM, E + 1), 256, SMEM1>>>();
    gemm2_kernel<<<dim3(H / BN, T / BM, E + 1), 256, SMEM2>>>(out);

    finalize_kernel<<<1, 256>>>(out);
}